// round 2
// baseline (speedup 1.0000x reference)
#include <cuda_runtime.h>
#include <cstdint>

// Problem constants
#define TT      512
#define BB      256
#define HH      128
#define EE      256
#define VV      82
#define HE      384     // HIDDEN + EMBED
#define G3H     384     // 3 gates * H
#define HPAD    144     // 128 + 4-per-32 skew

// Precomputed x-projection table: xtable[v][g*H+u], g: 0=f, 1=o, 2=c_tilde
__device__ float g_xtable[VV * G3H];

// ---------------------------------------------------------------------------
// packed f32x2 helpers
// ---------------------------------------------------------------------------
__device__ __forceinline__ unsigned long long ffma2(unsigned long long a,
                                                    unsigned long long b,
                                                    unsigned long long c) {
    unsigned long long d;
    asm("fma.rn.f32x2 %0, %1, %2, %3;" : "=l"(d) : "l"(a), "l"(b), "l"(c));
    return d;
}

__device__ __forceinline__ float2 unpack2(unsigned long long v) {
    float2 r;
    asm("mov.b64 {%0, %1}, %2;" : "=f"(r.x), "=f"(r.y) : "l"(v));
    return r;
}

__device__ __forceinline__ float sigmoid_f(float x) {
    return __fdividef(1.0f, 1.0f + __expf(-x));
}
__device__ __forceinline__ float tanh_f(float x) {
    return 1.0f - __fdividef(2.0f, __expf(2.0f * x) + 1.0f);
}

// ---------------------------------------------------------------------------
// Kernel 1: xtable[v][g*128+u] = sum_k emb[v][k] * W_g[u][128+k]
// Gate order g: 0 = W_f, 1 = W_o, 2 = W_c
// ---------------------------------------------------------------------------
__global__ void xtable_kernel(const float* __restrict__ emb,
                              const float* __restrict__ Wf,
                              const float* __restrict__ Wc,
                              const float* __restrict__ Wo) {
    int v = blockIdx.x;          // 0..81
    int j = threadIdx.x;         // 0..383
    int g = j >> 7;
    int u = j & 127;
    const float* W = (g == 0) ? Wf : ((g == 1) ? Wo : Wc);
    const float4* wrow = reinterpret_cast<const float4*>(W + (size_t)u * HE + HH);
    const float4* e = reinterpret_cast<const float4*>(emb + (size_t)v * EE);
    float s = 0.0f;
#pragma unroll
    for (int k = 0; k < EE / 4; k++) {
        float4 a = e[k];
        float4 b = wrow[k];
        s += a.x * b.x + a.y * b.y + a.z * b.z + a.w * b.w;
    }
    g_xtable[v * G3H + j] = s;
}

// ---------------------------------------------------------------------------
// Kernel 2: recurrence.
// 128 blocks x 768 threads (24 warps); each block owns 2 batch rows.
// Lane layout: lane = q*8 + s, q = K-quarter (0..3), s = unit-slot (0..7).
// Thread owns W rows (up, up+1) where up = warp*16 + s*2, restricted to
// K-columns [q*32, q*32+32). Partial sums reduced across q via shfl.bfly.
// ---------------------------------------------------------------------------
__global__ void __launch_bounds__(768, 1)
lstm_kernel(const int*   __restrict__ tokens,   // [B, T]
            const float* __restrict__ Wf,
            const float* __restrict__ Wc,
            const float* __restrict__ Wo,
            const float* __restrict__ clfW,     // [V, H]
            const float* __restrict__ clfb,     // [V]
            float* __restrict__ out) {
    __shared__ __align__(16) float sh_h[2][HPAD];   // skewed h storage
    __shared__ __align__(8)  float sh_g[2][G3H];
    __shared__ int   sh_tok[2][TT];

    const int j    = threadIdx.x;        // 0..767
    const int lane = j & 31;
    const int warp = j >> 5;             // 0..23
    const int q    = lane >> 3;          // K-quarter 0..3
    const int s    = lane & 7;           // unit slot 0..7
    const int up   = warp * 16 + s * 2;  // even unit-pair base, 0..382
    const int g    = up >> 7;            // gate: 0=f, 1=o, 2=ct
    const int b0   = blockIdx.x * 2;

    // ---- load this thread's two W-row K-quarter segments (32 floats each) ----
    const float* Wsel = (g == 0) ? Wf : ((g == 1) ? Wo : Wc);
    unsigned long long wA[16], wB[16];
    {
        const ulonglong2* pA = reinterpret_cast<const ulonglong2*>(
            Wsel + (size_t)(up & 127) * HE + q * 32);
        const ulonglong2* pB = reinterpret_cast<const ulonglong2*>(
            Wsel + (size_t)((up + 1) & 127) * HE + q * 32);
#pragma unroll
        for (int i = 0; i < 8; i++) {
            ulonglong2 ta = pA[i]; wA[2 * i] = ta.x; wA[2 * i + 1] = ta.y;
            ulonglong2 tb = pB[i]; wB[2 * i] = tb.x; wB[2 * i + 1] = tb.y;
        }
    }

    // ---- init h = 0; stage tokens into smem ----
    for (int i = j; i < 2 * HPAD; i += 768) (&sh_h[0][0])[i] = 0.0f;
    for (int i = j; i < 2 * TT; i += 768)
        (&sh_tok[0][0])[i] = tokens[(size_t)(b0 + i / TT) * TT + (i % TT)];
    __syncthreads();

    float creg = 0.0f;   // cell state for phase-2 threads (j < 256)

    const size_t gateSz = (size_t)TT * BB * HH;
    float* f_out = out + (size_t)BB * VV;
    float* o_out = f_out + gateSz;
    float* c_out = o_out + gateSz;

    // per-thread smem read bases for h quarters (skewed: q*36 floats)
    const ulonglong2* h0base = reinterpret_cast<const ulonglong2*>(&sh_h[0][q * 36]);
    const ulonglong2* h1base = reinterpret_cast<const ulonglong2*>(&sh_h[1][q * 36]);

    for (int t = 0; t < TT; t++) {
        // prefetch x-parts (L2-resident table); only q==0 lanes need them
        float2 x0 = make_float2(0.f, 0.f), x1 = make_float2(0.f, 0.f);
        if (q == 0) {
            const int tok0 = sh_tok[0][t];
            const int tok1 = sh_tok[1][t];
            x0 = *reinterpret_cast<const float2*>(&g_xtable[tok0 * G3H + up]);
            x1 = *reinterpret_cast<const float2*>(&g_xtable[tok1 * G3H + up]);
        }

        unsigned long long aA0 = 0ull, aB0 = 0ull, aA1 = 0ull, aB1 = 0ull;
#pragma unroll
        for (int i = 0; i < 8; i++) {
            ulonglong2 v = h0base[i];
            aA0 = ffma2(v.x, wA[2 * i], aA0);
            aA0 = ffma2(v.y, wA[2 * i + 1], aA0);
            aB0 = ffma2(v.x, wB[2 * i], aB0);
            aB0 = ffma2(v.y, wB[2 * i + 1], aB0);
        }
#pragma unroll
        for (int i = 0; i < 8; i++) {
            ulonglong2 v = h1base[i];
            aA1 = ffma2(v.x, wA[2 * i], aA1);
            aA1 = ffma2(v.y, wA[2 * i + 1], aA1);
            aB1 = ffma2(v.x, wB[2 * i], aB1);
            aB1 = ffma2(v.y, wB[2 * i + 1], aB1);
        }
        float2 pA0 = unpack2(aA0), pB0 = unpack2(aB0);
        float2 pA1 = unpack2(aA1), pB1 = unpack2(aB1);
        float sA0 = pA0.x + pA0.y;
        float sB0 = pB0.x + pB0.y;
        float sA1 = pA1.x + pA1.y;
        float sB1 = pB1.x + pB1.y;

        // reduce across K-quarters (lane bits 3,4)
        sA0 += __shfl_xor_sync(0xffffffffu, sA0, 8);
        sB0 += __shfl_xor_sync(0xffffffffu, sB0, 8);
        sA1 += __shfl_xor_sync(0xffffffffu, sA1, 8);
        sB1 += __shfl_xor_sync(0xffffffffu, sB1, 8);
        sA0 += __shfl_xor_sync(0xffffffffu, sA0, 16);
        sB0 += __shfl_xor_sync(0xffffffffu, sB0, 16);
        sA1 += __shfl_xor_sync(0xffffffffu, sA1, 16);
        sB1 += __shfl_xor_sync(0xffffffffu, sB1, 16);

        if (q == 0) {
            float vA0 = sA0 + x0.x, vB0 = sB0 + x0.y;
            float vA1 = sA1 + x1.x, vB1 = sB1 + x1.y;
            if (g == 2) {
                vA0 = tanh_f(vA0); vB0 = tanh_f(vB0);
                vA1 = tanh_f(vA1); vB1 = tanh_f(vB1);
            } else {
                vA0 = sigmoid_f(vA0); vB0 = sigmoid_f(vB0);
                vA1 = sigmoid_f(vA1); vB1 = sigmoid_f(vB1);
            }
            *reinterpret_cast<float2*>(&sh_g[0][up]) = make_float2(vA0, vB0);
            *reinterpret_cast<float2*>(&sh_g[1][up]) = make_float2(vA1, vB1);
        }
        __syncthreads();

        if (j < 256) {
            const int b  = j >> 7;
            const int uu = j & 127;
            const float fv  = sh_g[b][uu];
            const float ov  = sh_g[b][HH + uu];
            const float ctv = sh_g[b][2 * HH + uu];
            creg = fv * creg + (1.0f - fv) * ctv;
            const float hn = ov * tanh_f(creg);
            sh_h[b][uu + (uu >> 5) * 4] = hn;       // skewed store
            const size_t base = ((size_t)t * BB + (b0 + b)) * HH + uu;
            f_out[base] = fv;
            o_out[base] = ov;
            c_out[base] = ctv;
        }
        __syncthreads();
    }

    // ---- logits: h_T @ clf_W.T + clf_b  (2 batches x 82 vocab) ----
    if (j < 2 * VV) {
        const int b = j / VV;
        const int v = j % VV;
        float sacc = clfb[v];
        const float* wc = clfW + (size_t)v * HH;
#pragma unroll 8
        for (int k = 0; k < HH; k++) sacc += sh_h[b][k + (k >> 5) * 4] * wc[k];
        out[(size_t)(b0 + b) * VV + v] = sacc;
    }
}

// ---------------------------------------------------------------------------
// kernel_launch
// Inputs (metadata order): batch_reviews(int32 [256,512]), emb(f32 [82,256]),
//   W_f(f32 [128,384]), W_c(f32 [128,384]), W_o(f32 [128,384]),
//   clf_W(f32 [82,128]), clf_b(f32 [82])
// Output (f32): logits [256*82] | f_all [512*256*128] | o_all | ct_all
// ---------------------------------------------------------------------------
extern "C" void kernel_launch(void* const* d_in, const int* in_sizes, int n_in,
                              void* d_out, int out_size) {
    const int*   tokens = (const int*)  d_in[0];
    const float* emb    = (const float*)d_in[1];
    const float* Wf     = (const float*)d_in[2];
    const float* Wc     = (const float*)d_in[3];
    const float* Wo     = (const float*)d_in[4];
    const float* clfW   = (const float*)d_in[5];
    const float* clfb   = (const float*)d_in[6];
    float* out = (float*)d_out;

    xtable_kernel<<<VV, G3H>>>(emb, Wf, Wc, Wo);
    lstm_kernel<<<BB / 2, 768>>>(tokens, Wf, Wc, Wo, clfW, clfb, out);
}

// round 3
// speedup vs baseline: 1.0031x; 1.0031x over previous
#include <cuda_runtime.h>
#include <cstdint>

// Problem constants
#define TT      512
#define BB      256
#define HH      128
#define EE      256
#define VV      82
#define HE      384     // HIDDEN + EMBED
#define G3H     384     // 3 gates * H
#define HPAD    144     // 128 + 4-per-32 skew

// Precomputed x-projection table: xtable[v][g*H+u], g: 0=f, 1=o, 2=c_tilde
__device__ float g_xtable[VV * G3H];

// ---------------------------------------------------------------------------
// packed f32x2 helpers
// ---------------------------------------------------------------------------
__device__ __forceinline__ unsigned long long ffma2(unsigned long long a,
                                                    unsigned long long b,
                                                    unsigned long long c) {
    unsigned long long d;
    asm("fma.rn.f32x2 %0, %1, %2, %3;" : "=l"(d) : "l"(a), "l"(b), "l"(c));
    return d;
}

__device__ __forceinline__ float2 unpack2(unsigned long long v) {
    float2 r;
    asm("mov.b64 {%0, %1}, %2;" : "=f"(r.x), "=f"(r.y) : "l"(v));
    return r;
}

__device__ __forceinline__ float sigmoid_f(float x) {
    return __fdividef(1.0f, 1.0f + __expf(-x));
}
__device__ __forceinline__ float tanh_f(float x) {
    return 1.0f - __fdividef(2.0f, __expf(2.0f * x) + 1.0f);
}

// ---------------------------------------------------------------------------
// Kernel 1: xtable[v][g*128+u] = sum_k emb[v][k] * W_g[u][128+k]
// Gate order g: 0 = W_f, 1 = W_o, 2 = W_c
// ---------------------------------------------------------------------------
__global__ void xtable_kernel(const float* __restrict__ emb,
                              const float* __restrict__ Wf,
                              const float* __restrict__ Wc,
                              const float* __restrict__ Wo) {
    int v = blockIdx.x;          // 0..81
    int j = threadIdx.x;         // 0..383
    int g = j >> 7;
    int u = j & 127;
    const float* W = (g == 0) ? Wf : ((g == 1) ? Wo : Wc);
    const float4* wrow = reinterpret_cast<const float4*>(W + (size_t)u * HE + HH);
    const float4* e = reinterpret_cast<const float4*>(emb + (size_t)v * EE);
    float s = 0.0f;
#pragma unroll
    for (int k = 0; k < EE / 4; k++) {
        float4 a = e[k];
        float4 b = wrow[k];
        s += a.x * b.x + a.y * b.y + a.z * b.z + a.w * b.w;
    }
    g_xtable[v * G3H + j] = s;
}

// ---------------------------------------------------------------------------
// Kernel 2: recurrence.
// 128 blocks x 768 threads (24 warps); each block owns 2 batch rows.
// Lane layout: lane = q*8 + s, q = K-quarter (0..3), s = unit-slot (0..7).
// Thread owns W rows (up, up+1) where up = warp*16 + s*2, restricted to
// K-columns [q*32, q*32+32). Partial sums reduced across q via shfl.bfly.
// ---------------------------------------------------------------------------
__global__ void __launch_bounds__(768, 1)
lstm_kernel(const int*   __restrict__ tokens,   // [B, T]
            const float* __restrict__ Wf,
            const float* __restrict__ Wc,
            const float* __restrict__ Wo,
            const float* __restrict__ clfW,     // [V, H]
            const float* __restrict__ clfb,     // [V]
            float* __restrict__ out) {
    __shared__ __align__(16) float sh_h[2][HPAD];   // skewed h storage
    __shared__ __align__(8)  float sh_g[2][G3H];
    __shared__ int   sh_tok[2][TT];

    const int j    = threadIdx.x;        // 0..767
    const int lane = j & 31;
    const int warp = j >> 5;             // 0..23
    const int q    = lane >> 3;          // K-quarter 0..3
    const int s    = lane & 7;           // unit slot 0..7
    const int up   = warp * 16 + s * 2;  // even unit-pair base, 0..382
    const int g    = up >> 7;            // gate: 0=f, 1=o, 2=ct
    const int b0   = blockIdx.x * 2;

    // ---- load this thread's two W-row K-quarter segments (32 floats each) ----
    const float* Wsel = (g == 0) ? Wf : ((g == 1) ? Wo : Wc);
    unsigned long long wA[16], wB[16];
    {
        const ulonglong2* pA = reinterpret_cast<const ulonglong2*>(
            Wsel + (size_t)(up & 127) * HE + q * 32);
        const ulonglong2* pB = reinterpret_cast<const ulonglong2*>(
            Wsel + (size_t)((up + 1) & 127) * HE + q * 32);
#pragma unroll
        for (int i = 0; i < 8; i++) {
            ulonglong2 ta = pA[i]; wA[2 * i] = ta.x; wA[2 * i + 1] = ta.y;
            ulonglong2 tb = pB[i]; wB[2 * i] = tb.x; wB[2 * i + 1] = tb.y;
        }
    }

    // ---- init h = 0; stage tokens into smem ----
    for (int i = j; i < 2 * HPAD; i += 768) (&sh_h[0][0])[i] = 0.0f;
    for (int i = j; i < 2 * TT; i += 768)
        (&sh_tok[0][0])[i] = tokens[(size_t)(b0 + i / TT) * TT + (i % TT)];
    __syncthreads();

    float creg = 0.0f;   // cell state for phase-2 threads (j < 256)

    const size_t gateSz = (size_t)TT * BB * HH;
    float* f_out = out + (size_t)BB * VV;
    float* o_out = f_out + gateSz;
    float* c_out = o_out + gateSz;

    // per-thread smem read bases for h quarters (skewed: q*36 floats)
    const ulonglong2* h0base = reinterpret_cast<const ulonglong2*>(&sh_h[0][q * 36]);
    const ulonglong2* h1base = reinterpret_cast<const ulonglong2*>(&sh_h[1][q * 36]);

    for (int t = 0; t < TT; t++) {
        // prefetch x-parts (L2-resident table); only q==0 lanes need them
        float2 x0 = make_float2(0.f, 0.f), x1 = make_float2(0.f, 0.f);
        if (q == 0) {
            const int tok0 = sh_tok[0][t];
            const int tok1 = sh_tok[1][t];
            x0 = *reinterpret_cast<const float2*>(&g_xtable[tok0 * G3H + up]);
            x1 = *reinterpret_cast<const float2*>(&g_xtable[tok1 * G3H + up]);
        }

        unsigned long long aA0 = 0ull, aB0 = 0ull, aA1 = 0ull, aB1 = 0ull;
#pragma unroll
        for (int i = 0; i < 8; i++) {
            ulonglong2 v = h0base[i];
            aA0 = ffma2(v.x, wA[2 * i], aA0);
            aA0 = ffma2(v.y, wA[2 * i + 1], aA0);
            aB0 = ffma2(v.x, wB[2 * i], aB0);
            aB0 = ffma2(v.y, wB[2 * i + 1], aB0);
        }
#pragma unroll
        for (int i = 0; i < 8; i++) {
            ulonglong2 v = h1base[i];
            aA1 = ffma2(v.x, wA[2 * i], aA1);
            aA1 = ffma2(v.y, wA[2 * i + 1], aA1);
            aB1 = ffma2(v.x, wB[2 * i], aB1);
            aB1 = ffma2(v.y, wB[2 * i + 1], aB1);
        }
        float2 pA0 = unpack2(aA0), pB0 = unpack2(aB0);
        float2 pA1 = unpack2(aA1), pB1 = unpack2(aB1);
        float sA0 = pA0.x + pA0.y;
        float sB0 = pB0.x + pB0.y;
        float sA1 = pA1.x + pA1.y;
        float sB1 = pB1.x + pB1.y;

        // reduce across K-quarters (lane bits 3,4)
        sA0 += __shfl_xor_sync(0xffffffffu, sA0, 8);
        sB0 += __shfl_xor_sync(0xffffffffu, sB0, 8);
        sA1 += __shfl_xor_sync(0xffffffffu, sA1, 8);
        sB1 += __shfl_xor_sync(0xffffffffu, sB1, 8);
        sA0 += __shfl_xor_sync(0xffffffffu, sA0, 16);
        sB0 += __shfl_xor_sync(0xffffffffu, sB0, 16);
        sA1 += __shfl_xor_sync(0xffffffffu, sA1, 16);
        sB1 += __shfl_xor_sync(0xffffffffu, sB1, 16);

        if (q == 0) {
            float vA0 = sA0 + x0.x, vB0 = sB0 + x0.y;
            float vA1 = sA1 + x1.x, vB1 = sB1 + x1.y;
            if (g == 2) {
                vA0 = tanh_f(vA0); vB0 = tanh_f(vB0);
                vA1 = tanh_f(vA1); vB1 = tanh_f(vB1);
            } else {
                vA0 = sigmoid_f(vA0); vB0 = sigmoid_f(vB0);
                vA1 = sigmoid_f(vA1); vB1 = sigmoid_f(vB1);
            }
            *reinterpret_cast<float2*>(&sh_g[0][up]) = make_float2(vA0, vB0);
            *reinterpret_cast<float2*>(&sh_g[1][up]) = make_float2(vA1, vB1);
        }
        __syncthreads();

        if (j < 256) {
            const int b  = j >> 7;
            const int uu = j & 127;
            const float fv  = sh_g[b][uu];
            const float ov  = sh_g[b][HH + uu];
            const float ctv = sh_g[b][2 * HH + uu];
            creg = fv * creg + (1.0f - fv) * ctv;
            const float hn = ov * tanh_f(creg);
            sh_h[b][uu + (uu >> 5) * 4] = hn;       // skewed store
            const size_t base = ((size_t)t * BB + (b0 + b)) * HH + uu;
            f_out[base] = fv;
            o_out[base] = ov;
            c_out[base] = ctv;
        }
        __syncthreads();
    }

    // ---- logits: h_T @ clf_W.T + clf_b  (2 batches x 82 vocab) ----
    if (j < 2 * VV) {
        const int b = j / VV;
        const int v = j % VV;
        float sacc = clfb[v];
        const float* wc = clfW + (size_t)v * HH;
#pragma unroll 8
        for (int k = 0; k < HH; k++) sacc += sh_h[b][k + (k >> 5) * 4] * wc[k];
        out[(size_t)(b0 + b) * VV + v] = sacc;
    }
}

// ---------------------------------------------------------------------------
// kernel_launch
// Inputs (metadata order): batch_reviews(int32 [256,512]), emb(f32 [82,256]),
//   W_f(f32 [128,384]), W_c(f32 [128,384]), W_o(f32 [128,384]),
//   clf_W(f32 [82,128]), clf_b(f32 [82])
// Output (f32): logits [256*82] | f_all [512*256*128] | o_all | ct_all
// ---------------------------------------------------------------------------
extern "C" void kernel_launch(void* const* d_in, const int* in_sizes, int n_in,
                              void* d_out, int out_size) {
    const int*   tokens = (const int*)  d_in[0];
    const float* emb    = (const float*)d_in[1];
    const float* Wf     = (const float*)d_in[2];
    const float* Wc     = (const float*)d_in[3];
    const float* Wo     = (const float*)d_in[4];
    const float* clfW   = (const float*)d_in[5];
    const float* clfb   = (const float*)d_in[6];
    float* out = (float*)d_out;

    xtable_kernel<<<VV, G3H>>>(emb, Wf, Wc, Wo);
    lstm_kernel<<<BB / 2, 768>>>(tokens, Wf, Wc, Wo, clfW, clfb, out);
}

// round 4
// speedup vs baseline: 1.2446x; 1.2407x over previous
#include <cuda_runtime.h>
#include <cstdint>

// Problem constants
#define TT      512
#define BB      256
#define HH      128
#define EE      256
#define VV      82
#define HE      384     // HIDDEN + EMBED
#define G3H     384     // 3 gates * H

// Precomputed x-projection table: xtable[v][g*H+u], g: 0=f, 1=o, 2=c_tilde
__device__ float g_xtable[VV * G3H];

// ---------------------------------------------------------------------------
// helpers
// ---------------------------------------------------------------------------
__device__ __forceinline__ unsigned long long ffma2(unsigned long long a,
                                                    unsigned long long b,
                                                    unsigned long long c) {
    unsigned long long d;
    asm("fma.rn.f32x2 %0, %1, %2, %3;" : "=l"(d) : "l"(a), "l"(b), "l"(c));
    return d;
}

__device__ __forceinline__ float2 unpack2(unsigned long long v) {
    float2 r;
    asm("mov.b64 {%0, %1}, %2;" : "=f"(r.x), "=f"(r.y) : "l"(v));
    return r;
}

__device__ __forceinline__ float sigmoid_f(float x) {
    return __fdividef(1.0f, 1.0f + __expf(-x));
}
__device__ __forceinline__ float tanh_f(float x) {
    return 1.0f - __fdividef(2.0f, __expf(2.0f * x) + 1.0f);
}

// ---------------------------------------------------------------------------
// Kernel 1: xtable[v][g*128+u] = sum_k emb[v][k] * W_g[u][128+k]
// Gate order g: 0 = f, 1 = o, 2 = c_tilde
// ---------------------------------------------------------------------------
__global__ void xtable_kernel(const float* __restrict__ emb,
                              const float* __restrict__ Wf,
                              const float* __restrict__ Wc,
                              const float* __restrict__ Wo) {
    int v = blockIdx.x;          // 0..81
    int j = threadIdx.x;         // 0..383
    int g = j >> 7;
    int u = j & 127;
    const float* W = (g == 0) ? Wf : ((g == 1) ? Wo : Wc);
    const float4* wrow = reinterpret_cast<const float4*>(W + (size_t)u * HE + HH);
    const float4* e = reinterpret_cast<const float4*>(emb + (size_t)v * EE);
    float s = 0.0f;
#pragma unroll
    for (int k = 0; k < EE / 4; k++) {
        float4 a = e[k];
        float4 b = wrow[k];
        s += a.x * b.x + a.y * b.y + a.z * b.z + a.w * b.w;
    }
    g_xtable[v * G3H + j] = s;
}

// ---------------------------------------------------------------------------
// Kernel 2: recurrence.
// 128 blocks x 512 threads (16 warps); block owns 2 batch rows.
// Thread = (unit u, K-quarter q):   lane = q*8 + s,  u = warp*8 + s.
// Owns W_f/W_o/W_c row u, K-cols [q*32, q*32+32) -> 96 W regs, no replication.
// Computes all 3 gate partials for BOTH batches from one h read.
// Butterfly allreduce over q -> every lane has all 6 gate sums.
// c lives in a register (q0 owns batch0, q3 owns batch1).
// h double-buffered in smem -> ONE __syncthreads per step.
// ---------------------------------------------------------------------------
__global__ void __launch_bounds__(512, 1)
lstm_kernel(const int*   __restrict__ tokens,   // [B, T]
            const float* __restrict__ Wf,
            const float* __restrict__ Wc,
            const float* __restrict__ Wo,
            const float* __restrict__ clfW,     // [V, H]
            const float* __restrict__ clfb,     // [V]
            float* __restrict__ out) {
    // [buf][batch][skewed 128]: quarter q stored at float offset q*36 (bank skew)
    __shared__ __align__(16) float sh_h[2][2][144];
    __shared__ int sh_tok[2][TT];

    const int j    = threadIdx.x;        // 0..511
    const int lane = j & 31;
    const int warp = j >> 5;             // 0..15
    const int q    = lane >> 3;          // K-quarter 0..3
    const int s    = lane & 7;
    const int u    = warp * 8 + s;       // unit 0..127
    const int b0   = blockIdx.x * 2;
    const int bsel = (q >= 2) ? 1 : 0;   // which batch this lane finalizes

    // ---- load W rows (3 gates), K-quarter segment: 3 x 16 packed f32x2 ----
    unsigned long long wf[16], wo[16], wc[16];
    {
        const ulonglong2* pf = reinterpret_cast<const ulonglong2*>(Wf + (size_t)u * HE + q * 32);
        const ulonglong2* po = reinterpret_cast<const ulonglong2*>(Wo + (size_t)u * HE + q * 32);
        const ulonglong2* pc = reinterpret_cast<const ulonglong2*>(Wc + (size_t)u * HE + q * 32);
#pragma unroll
        for (int i = 0; i < 8; i++) {
            ulonglong2 tf = pf[i]; wf[2 * i] = tf.x; wf[2 * i + 1] = tf.y;
            ulonglong2 to = po[i]; wo[2 * i] = to.x; wo[2 * i + 1] = to.y;
            ulonglong2 tc = pc[i]; wc[2 * i] = tc.x; wc[2 * i + 1] = tc.y;
        }
    }

    // ---- init h buffers = 0; stage tokens ----
    for (int i = j; i < 2 * 2 * 144; i += 512) (&sh_h[0][0][0])[i] = 0.0f;
    for (int i = j; i < 2 * TT; i += 512)
        (&sh_tok[0][0])[i] = tokens[(size_t)(b0 + (i >> 9)) * TT + (i & 511)];
    __syncthreads();

    float creg = 0.0f;                   // cell state (q0: batch0, q3: batch1)

    const size_t gateSz = (size_t)TT * BB * HH;
    float* f_out = out + (size_t)BB * VV;
    float* o_out = f_out + gateSz;
    float* c_out = o_out + gateSz;

    const int qoff = q * 36;             // skewed smem quarter base

    for (int t = 0; t < TT; t++) {
        const int p = t & 1;             // read buffer; write 1-p

        // x-part loads for this lane's batch (L1/L2-resident table) - issue early
        const int tok = sh_tok[bsel][t];
        const float* xr = &g_xtable[tok * G3H + u];
        const float xf = __ldg(xr);
        const float xo = __ldg(xr + HH);
        const float xc = __ldg(xr + 2 * HH);

        const ulonglong2* h0p = reinterpret_cast<const ulonglong2*>(&sh_h[p][0][qoff]);
        const ulonglong2* h1p = reinterpret_cast<const ulonglong2*>(&sh_h[p][1][qoff]);

        unsigned long long af0 = 0ull, ao0 = 0ull, ac0 = 0ull;
        unsigned long long af1 = 0ull, ao1 = 0ull, ac1 = 0ull;
#pragma unroll
        for (int i = 0; i < 8; i++) {
            ulonglong2 v = h0p[i];
            af0 = ffma2(v.x, wf[2 * i], af0); af0 = ffma2(v.y, wf[2 * i + 1], af0);
            ao0 = ffma2(v.x, wo[2 * i], ao0); ao0 = ffma2(v.y, wo[2 * i + 1], ao0);
            ac0 = ffma2(v.x, wc[2 * i], ac0); ac0 = ffma2(v.y, wc[2 * i + 1], ac0);
        }
#pragma unroll
        for (int i = 0; i < 8; i++) {
            ulonglong2 v = h1p[i];
            af1 = ffma2(v.x, wf[2 * i], af1); af1 = ffma2(v.y, wf[2 * i + 1], af1);
            ao1 = ffma2(v.x, wo[2 * i], ao1); ao1 = ffma2(v.y, wo[2 * i + 1], ao1);
            ac1 = ffma2(v.x, wc[2 * i], ac1); ac1 = ffma2(v.y, wc[2 * i + 1], ac1);
        }

        // horizontal + butterfly allreduce across K-quarters (lane bits 3,4)
        float2 P;
        P = unpack2(af0); float sf0 = P.x + P.y;
        P = unpack2(ao0); float so0 = P.x + P.y;
        P = unpack2(ac0); float sc0 = P.x + P.y;
        P = unpack2(af1); float sf1 = P.x + P.y;
        P = unpack2(ao1); float so1 = P.x + P.y;
        P = unpack2(ac1); float sc1 = P.x + P.y;
        sf0 += __shfl_xor_sync(0xffffffffu, sf0, 8);
        so0 += __shfl_xor_sync(0xffffffffu, so0, 8);
        sc0 += __shfl_xor_sync(0xffffffffu, sc0, 8);
        sf1 += __shfl_xor_sync(0xffffffffu, sf1, 8);
        so1 += __shfl_xor_sync(0xffffffffu, so1, 8);
        sc1 += __shfl_xor_sync(0xffffffffu, sc1, 8);
        sf0 += __shfl_xor_sync(0xffffffffu, sf0, 16);
        so0 += __shfl_xor_sync(0xffffffffu, so0, 16);
        sc0 += __shfl_xor_sync(0xffffffffu, sc0, 16);
        sf1 += __shfl_xor_sync(0xffffffffu, sf1, 16);
        so1 += __shfl_xor_sync(0xffffffffu, so1, 16);
        sc1 += __shfl_xor_sync(0xffffffffu, sc1, 16);

        // this lane's batch pre-activations
        const float sf = (bsel ? sf1 : sf0) + xf;
        const float so = (bsel ? so1 : so0) + xo;
        const float sc = (bsel ? sc1 : sc0) + xc;

        const float gf = sigmoid_f(sf);
        const float go = sigmoid_f(so);
        const float gc = tanh_f(sc);

        // c/h update: q0 owns batch0, q3 owns batch1 (c in register)
        if (q == 0 || q == 3) {
            creg = gf * creg + (1.0f - gf) * gc;
            const float hn = go * tanh_f(creg);
            sh_h[1 - p][bsel][u + (u >> 5) * 4] = hn;   // skewed store
        }

        // gate stores, split across q-lanes (each <=2 STG)
        const size_t base = ((size_t)t * BB + (b0 + bsel)) * HH + u;
        if (q == 0) { f_out[base] = gf; }
        else if (q == 1) { o_out[base] = go; c_out[base] = gc; }
        else if (q == 2) { f_out[base] = gf; o_out[base] = go; }
        else { c_out[base] = gc; }

        __syncthreads();
    }

    // ---- logits: h_T @ clf_W.T + clf_b  (final h in buffer 0) ----
    if (j < 2 * VV) {
        const int b = j / VV;
        const int v = j % VV;
        float sacc = clfb[v];
        const float* wcf = clfW + (size_t)v * HH;
#pragma unroll 8
        for (int k = 0; k < HH; k++)
            sacc += sh_h[0][b][k + (k >> 5) * 4] * wcf[k];
        out[(size_t)(b0 + b) * VV + v] = sacc;
    }
}

// ---------------------------------------------------------------------------
// kernel_launch
// Inputs (metadata order): batch_reviews(int32 [256,512]), emb(f32 [82,256]),
//   W_f(f32 [128,384]), W_c(f32 [128,384]), W_o(f32 [128,384]),
//   clf_W(f32 [82,128]), clf_b(f32 [82])
// Output (f32): logits [256*82] | f_all [512*256*128] | o_all | ct_all
// ---------------------------------------------------------------------------
extern "C" void kernel_launch(void* const* d_in, const int* in_sizes, int n_in,
                              void* d_out, int out_size) {
    const int*   tokens = (const int*)  d_in[0];
    const float* emb    = (const float*)d_in[1];
    const float* Wf     = (const float*)d_in[2];
    const float* Wc     = (const float*)d_in[3];
    const float* Wo     = (const float*)d_in[4];
    const float* clfW   = (const float*)d_in[5];
    const float* clfb   = (const float*)d_in[6];
    float* out = (float*)d_out;

    xtable_kernel<<<VV, G3H>>>(emb, Wf, Wc, Wo);
    lstm_kernel<<<BB / 2, 512>>>(tokens, Wf, Wc, Wo, clfW, clfb, out);
}

// round 5
// speedup vs baseline: 1.4658x; 1.1778x over previous
#include <cuda_runtime.h>
#include <cstdint>

// Problem constants
#define TT      512
#define BB      256
#define HH      128
#define EE      256
#define VV      82
#define HE      384     // HIDDEN + EMBED
#define G3H     384     // 3 gates * H

// Precomputed x-projection table: xtable[v][g*H+u], g: 0=f, 1=o, 2=c_tilde
__device__ float g_xtable[VV * G3H];

// ---------------------------------------------------------------------------
// helpers
// ---------------------------------------------------------------------------
__device__ __forceinline__ unsigned long long ffma2(unsigned long long a,
                                                    unsigned long long b,
                                                    unsigned long long c) {
    unsigned long long d;
    asm("fma.rn.f32x2 %0, %1, %2, %3;" : "=l"(d) : "l"(a), "l"(b), "l"(c));
    return d;
}

__device__ __forceinline__ float2 unpack2(unsigned long long v) {
    float2 r;
    asm("mov.b64 {%0, %1}, %2;" : "=f"(r.x), "=f"(r.y) : "l"(v));
    return r;
}

__device__ __forceinline__ float sigmoid_f(float x) {
    return __fdividef(1.0f, 1.0f + __expf(-x));
}
__device__ __forceinline__ float tanh_f(float x) {
    return 1.0f - __fdividef(2.0f, __expf(2.0f * x) + 1.0f);
}

// ---------------------------------------------------------------------------
// Kernel 1: xtable[v][g*128+u] = sum_k emb[v][k] * W_g[u][128+k]
// ---------------------------------------------------------------------------
__global__ void xtable_kernel(const float* __restrict__ emb,
                              const float* __restrict__ Wf,
                              const float* __restrict__ Wc,
                              const float* __restrict__ Wo) {
    int v = blockIdx.x;          // 0..81
    int j = threadIdx.x;         // 0..383
    int g = j >> 7;
    int u = j & 127;
    const float* W = (g == 0) ? Wf : ((g == 1) ? Wo : Wc);
    const float4* wrow = reinterpret_cast<const float4*>(W + (size_t)u * HE + HH);
    const float4* e = reinterpret_cast<const float4*>(emb + (size_t)v * EE);
    float s = 0.0f;
#pragma unroll
    for (int k = 0; k < EE / 4; k++) {
        float4 a = e[k];
        float4 b = wrow[k];
        s += a.x * b.x + a.y * b.y + a.z * b.z + a.w * b.w;
    }
    g_xtable[v * G3H + j] = s;
}

// ---------------------------------------------------------------------------
// Kernel 2: recurrence. 128 blocks x 512 threads; block owns 2 batch rows.
// Lane bits: s = lane&7 (unit slot), bsel = bit3 (owned batch),
//            kh = bit4 (owned K-half), qq = (kh<<1)|bsel (W K-quarter).
// Thread owns W_f/W_o/W_c row u = warp*8+s, K-cols [qq*32, qq*32+32).
// FMA: 6 quarter-partials (3 gates x 2 batches). Reduction:
//   round1 (xor 8): send the NOT-owned batch's partials; partner's incoming
//     value is my missing quarter for MY batch -> 3 shfl, 3 live values.
//   round2 (xor 16): plain K-half reduce -> 3 shfl.
// kh==0 lanes carry c in a register and write h (double-buffered smem).
// ONE __syncthreads per step.
// ---------------------------------------------------------------------------
__global__ void __launch_bounds__(512, 1)
lstm_kernel(const int*   __restrict__ tokens,   // [B, T]
            const float* __restrict__ Wf,
            const float* __restrict__ Wc,
            const float* __restrict__ Wo,
            const float* __restrict__ clfW,     // [V, H]
            const float* __restrict__ clfb,     // [V]
            float* __restrict__ out) {
    // [buf][batch][skewed 128]: quarter qq at float offset qq*36 (bank skew)
    __shared__ __align__(16) float sh_h[2][2][144];
    __shared__ int sh_tok[2][TT];     // PRE-SCALED: tok * G3H

    const int j    = threadIdx.x;        // 0..511
    const int lane = j & 31;
    const int warp = j >> 5;             // 0..15
    const int s    = lane & 7;
    const int bsel = (lane >> 3) & 1;    // owned batch
    const int kh   = lane >> 4;          // owned K-half
    const int qq   = (lane >> 3) & 3;    // W K-quarter = (kh<<1)|bsel
    const int u    = warp * 8 + s;       // unit 0..127
    const int b0   = blockIdx.x * 2;

    // ---- load W rows (3 gates), K-quarter segment: 3 x 16 packed f32x2 ----
    unsigned long long wf[16], wo[16], wc[16];
    {
        const ulonglong2* pf = reinterpret_cast<const ulonglong2*>(Wf + (size_t)u * HE + qq * 32);
        const ulonglong2* po = reinterpret_cast<const ulonglong2*>(Wo + (size_t)u * HE + qq * 32);
        const ulonglong2* pc = reinterpret_cast<const ulonglong2*>(Wc + (size_t)u * HE + qq * 32);
#pragma unroll
        for (int i = 0; i < 8; i++) {
            ulonglong2 tf = pf[i]; wf[2 * i] = tf.x; wf[2 * i + 1] = tf.y;
            ulonglong2 to = po[i]; wo[2 * i] = to.x; wo[2 * i + 1] = to.y;
            ulonglong2 tc = pc[i]; wc[2 * i] = tc.x; wc[2 * i + 1] = tc.y;
        }
    }

    // ---- init h buffers = 0; stage PRE-SCALED tokens ----
    for (int i = j; i < 2 * 2 * 144; i += 512) (&sh_h[0][0][0])[i] = 0.0f;
    for (int i = j; i < 2 * TT; i += 512)
        (&sh_tok[0][0])[i] = tokens[(size_t)(b0 + (i >> 9)) * TT + (i & 511)] * G3H;
    __syncthreads();

    float creg = 0.0f;                   // cell state (kh==0 lanes)

    const size_t gateSz = (size_t)TT * BB * HH;
    float* __restrict__ f_out = out + (size_t)BB * VV;
    float* __restrict__ o_out = f_out + gateSz;
    float* __restrict__ c_out = o_out + gateSz;

    const float* gx = g_xtable + u;      // per-thread xtable base
    const int qoff = qq * 36;            // skewed smem quarter base (floats)
    int off = (b0 + bsel) * HH + u;      // 32-bit running output offset

    const unsigned FULL = 0xffffffffu;

    // one step: read h from buffer rb, write h to buffer wb
    auto step = [&](int t, int rb, int wb) {
        // x-part loads for owned batch (L1/L2-resident), issued before FMA
        const int toff = sh_tok[bsel][t];
        const float xf = __ldg(gx + toff);
        const float xo = __ldg(gx + toff + HH);
        const float xc = __ldg(gx + toff + 2 * HH);

        const ulonglong2* h0p = reinterpret_cast<const ulonglong2*>(&sh_h[rb][0][qoff]);
        const ulonglong2* h1p = reinterpret_cast<const ulonglong2*>(&sh_h[rb][1][qoff]);

        unsigned long long af0 = 0ull, ao0 = 0ull, ac0 = 0ull;
        unsigned long long af1 = 0ull, ao1 = 0ull, ac1 = 0ull;
#pragma unroll
        for (int i = 0; i < 8; i++) {
            ulonglong2 v = h0p[i];
            af0 = ffma2(v.x, wf[2 * i], af0); af0 = ffma2(v.y, wf[2 * i + 1], af0);
            ao0 = ffma2(v.x, wo[2 * i], ao0); ao0 = ffma2(v.y, wo[2 * i + 1], ao0);
            ac0 = ffma2(v.x, wc[2 * i], ac0); ac0 = ffma2(v.y, wc[2 * i + 1], ac0);
        }
#pragma unroll
        for (int i = 0; i < 8; i++) {
            ulonglong2 v = h1p[i];
            af1 = ffma2(v.x, wf[2 * i], af1); af1 = ffma2(v.y, wf[2 * i + 1], af1);
            ao1 = ffma2(v.x, wo[2 * i], ao1); ao1 = ffma2(v.y, wo[2 * i + 1], ao1);
            ac1 = ffma2(v.x, wc[2 * i], ac1); ac1 = ffma2(v.y, wc[2 * i + 1], ac1);
        }

        // horizontal folds
        float2 P;
        P = unpack2(af0); const float sf0 = P.x + P.y;
        P = unpack2(ao0); const float so0 = P.x + P.y;
        P = unpack2(ac0); const float sc0 = P.x + P.y;
        P = unpack2(af1); const float sf1 = P.x + P.y;
        P = unpack2(ao1); const float so1 = P.x + P.y;
        P = unpack2(ac1); const float sc1 = P.x + P.y;

        // round 1 (xor 8): send NOT-owned batch's partial; recv = my missing
        // quarter for MY batch (partner quarter = qq^1).
        const float rf = __shfl_xor_sync(FULL, bsel ? sf0 : sf1, 8);
        const float ro = __shfl_xor_sync(FULL, bsel ? so0 : so1, 8);
        const float rc = __shfl_xor_sync(FULL, bsel ? sc0 : sc1, 8);
        float Sf = (bsel ? sf1 : sf0) + rf;
        float So = (bsel ? so1 : so0) + ro;
        float Sc = (bsel ? sc1 : sc0) + rc;

        // round 2 (xor 16): K-half reduce (same owned batch)
        Sf += __shfl_xor_sync(FULL, Sf, 16);
        So += __shfl_xor_sync(FULL, So, 16);
        Sc += __shfl_xor_sync(FULL, Sc, 16);

        Sf += xf; So += xo; Sc += xc;

        const float gf = sigmoid_f(Sf);
        const float go = sigmoid_f(So);
        const float gc = tanh_f(Sc);

        // c/h update by kh==0 lanes; h store skewed into write buffer
        if (kh == 0) {
            creg = gf * (creg - gc) + gc;
            const float hn = go * tanh_f(creg);
            sh_h[wb][bsel][u + (u >> 5) * 4] = hn;
            f_out[off] = gf;
        } else {
            o_out[off] = go;
            c_out[off] = gc;
        }
        off += BB * HH;

        __syncthreads();
    };

#pragma unroll 1
    for (int t = 0; t < TT; t += 2) {
        step(t, 0, 1);
        step(t + 1, 1, 0);
    }

    // ---- logits: h_T @ clf_W.T + clf_b  (final h in buffer 0) ----
    if (j < 2 * VV) {
        const int b = j / VV;
        const int v = j % VV;
        float sacc = clfb[v];
        const float* wcf = clfW + (size_t)v * HH;
#pragma unroll 8
        for (int k = 0; k < HH; k++)
            sacc += sh_h[0][b][k + (k >> 5) * 4] * wcf[k];
        out[(size_t)(b0 + b) * VV + v] = sacc;
    }
}

// ---------------------------------------------------------------------------
// kernel_launch
// Inputs (metadata order): batch_reviews(int32 [256,512]), emb(f32 [82,256]),
//   W_f(f32 [128,384]), W_c(f32 [128,384]), W_o(f32 [128,384]),
//   clf_W(f32 [82,128]), clf_b(f32 [82])
// Output (f32): logits [256*82] | f_all [512*256*128] | o_all | ct_all
// ---------------------------------------------------------------------------
extern "C" void kernel_launch(void* const* d_in, const int* in_sizes, int n_in,
                              void* d_out, int out_size) {
    const int*   tokens = (const int*)  d_in[0];
    const float* emb    = (const float*)d_in[1];
    const float* Wf     = (const float*)d_in[2];
    const float* Wc     = (const float*)d_in[3];
    const float* Wo     = (const float*)d_in[4];
    const float* clfW   = (const float*)d_in[5];
    const float* clfb   = (const float*)d_in[6];
    float* out = (float*)d_out;

    xtable_kernel<<<VV, G3H>>>(emb, Wf, Wc, Wo);
    lstm_kernel<<<BB / 2, 512>>>(tokens, Wf, Wc, Wo, clfW, clfb, out);
}